// round 14
// baseline (speedup 1.0000x reference)
#include <cuda_runtime.h>
#include <cuda_fp16.h>
#include <cstdint>
#include <cstddef>

// Correlation as band-Gram fp16 mma.sync GEMM (m16n8k16, fp32 accumulate).
// Pass 1: reformat d2 -> g_B, per (b,row): [par][t:7][kp2:3][lane:32][e:4].
// Pass 2: block = (y-pair, b), 384 thr, 2 blocks/SM. Rows y0, y0+2 share B
//   rows. COMPRESSED step loop: only steps with a valid B row run; uncovered
//   (y,i) outputs are zero-filled in a prologue. B rows via 3-deep cp.async
//   (distance 2); stage in output coords, one barrier per step.

#define NT   384
#define XROW 100                           // stage row stride (floats)
#define STAGE_H (21 * XROW)                // 2100 floats per y-half
#define STAGE_FLOATS (2 * STAGE_H)         // 4200 per buffer
#define B_U32   5376                       // u32 words per row (2 par x 2688)
#define B_BYTES 21504
#define NBUF    3
#define STAGE_OFF_B (NBUF * B_BYTES)       // 64512
#define SMEM_BYTES (STAGE_OFF_B + 2 * STAGE_FLOATS * 4)   // 98112 -> 2 blk/SM

#define GB_N 2752512                       // 8*64*5376
__device__ uint32_t g_B[GB_N];

__device__ __forceinline__ uint32_t packh2(float a, float b) {
    __half2 h = __floats2half2_rn(a, b);
    return *(uint32_t*)&h;
}
__device__ __forceinline__ uint32_t s2u(const void* p) {
    uint32_t a;
    asm("{ .reg .u64 t; cvta.to.shared.u64 t, %1; cvt.u32.u64 %0, t; }"
        : "=r"(a) : "l"(p));
    return a;
}
__device__ __forceinline__ void mma16(float* c, const uint32_t* a,
                                      uint32_t b0, uint32_t b1) {
    asm volatile(
        "mma.sync.aligned.m16n8k16.row.col.f32.f16.f16.f32 "
        "{%0,%1,%2,%3}, {%4,%5,%6,%7}, {%8,%9}, {%0,%1,%2,%3};"
        : "+f"(c[0]), "+f"(c[1]), "+f"(c[2]), "+f"(c[3])
        : "r"(a[0]), "r"(a[1]), "r"(a[2]), "r"(a[3]), "r"(b0), "r"(b1));
}

// ---------------- pass 1: reformat d2 -> g_B (smem transpose) --------------
__global__ void __launch_bounds__(256) reformat(const float* __restrict__ d2) {
    __shared__ float t[96 * 100];
    const int td  = threadIdx.x;
    const int row = blockIdx.x & 63;
    const int b   = blockIdx.x >> 6;

    const float* src = d2 + ((size_t)b * 96 * 64 + row) * 96;
    #pragma unroll
    for (int it = 0; it < 9; ++it) {
        int lin = it * 256 + td;
        int c = lin / 24, xq = lin - c * 24;
        float4 v = *(const float4*)(src + (size_t)c * 6144 + 4 * xq);
        *(float4*)(t + c * 100 + 4 * xq) = v;
    }
    __syncthreads();

    uint32_t* dst = g_B + (size_t)(b * 64 + row) * B_U32;
    #pragma unroll
    for (int it = 0; it < 21; ++it) {      // 5376 words
        int lin = it * 256 + td;
        int e = lin & 3;
        int l = (lin >> 2) & 31;
        int blk = lin >> 7;                // ((par*7 + tt)*3 + kp2)
        int kp2 = blk % 3, pt = blk / 3;
        int tt = pt % 7, par = pt / 7;
        int g = l >> 2, q = l & 3;
        int kp = 2 * kp2 + (e >> 1);
        int c = 16 * kp + 2 * q + 8 * (e & 1);
        int x = 16 * tt + 2 * g - 4 + par;
        float v0 = 0.f, v1 = 0.f;
        if ((unsigned)x < 96u) { v0 = t[c * 100 + x]; v1 = t[(c + 1) * 100 + x]; }
        dst[lin] = packh2(v0, v1);
    }
}

// ---------------- pass 2: paired-y GEMM, compressed step range -------------
__device__ __forceinline__ void writeout_half(
    float* __restrict__ out, const float* __restrict__ stb,
    int b, int yv, int iv, int td)
{
    if ((unsigned)iv >= 21u) return;
    float* ob = out + ((size_t)(b * 441 + iv * 21) * 64 + yv) * 96;
    #pragma unroll
    for (int rep = 0; rep < 2; ++rep) {
        int uu = td + NT * rep;
        if (uu < 504) {
            int j = uu / 24, xq = uu - j * 24;
            float4 v = *(const float4*)(stb + j * XROW + 4 * xq);
            __stcs((float4*)(ob + (size_t)j * 6144 + 4 * xq), v);
        }
    }
}

__global__ void __launch_bounds__(NT, 2) corr_mma(
    const float* __restrict__ d1,
    const float* __restrict__ s1, const float* __restrict__ s2,
    const float* __restrict__ osc, float* __restrict__ out)
{
    extern __shared__ char smc[];
    uint32_t* bsm = (uint32_t*)smc;                  // [3][B_U32]
    float* stage = (float*)(smc + STAGE_OFF_B);      // [2 buf][2h][21 j][XROW]
    const uint32_t bsm_u = s2u(smc);

    const int td = threadIdx.x;
    const int w = td >> 5, l = td & 31;
    const int h = w / 6, w6 = w % 6, m = w6 >> 1, par = w6 & 1;
    const int g = l >> 2, q = l & 3;
    const int t0 = (m == 0) ? 0 : ((m == 1) ? 1 : 3);
    const int nt = (m == 1) ? 5 : 4;

    const int yp = blockIdx.x;
    const int y0 = 4 * (yp >> 1) + (yp & 1);
    const int b = blockIdx.y;
    const int y = y0 + 2 * h;

    // valid step range: B row r = y0 + 2s - 20 in [0, 64)
    const int s_lo = (y0 < 21) ? ((21 - y0) >> 1) : 0;
    const int s_hi_raw = (83 - y0) >> 1;
    const int SC = (s_hi_raw < 21) ? s_hi_raw : 21;  // last compute step

    // ---- prologue: zero-fill outputs never computed ----
    {
        const int i0_lo = s_lo;
        const int i0_hi = (s_hi_raw < 20) ? s_hi_raw : 20;
        const int i1_lo = (s_lo > 0) ? (s_lo - 1) : 0;
        const int i1_hi = (s_hi_raw - 1 < 20) ? (s_hi_raw - 1) : 20;
        const float4 z4 = make_float4(0.f, 0.f, 0.f, 0.f);
        #pragma unroll
        for (int hh = 0; hh < 2; ++hh) {
            int lo = hh ? i1_lo : i0_lo, hi = hh ? i1_hi : i0_hi;
            int yv = y0 + 2 * hh;
            for (int i = 0; i < 21; ++i) {
                if (i >= lo && i <= hi) continue;
                #pragma unroll
                for (int rep = 0; rep < 2; ++rep) {
                    int uu = td + NT * rep;
                    if (uu < 504) {
                        int j = uu / 24, xq = uu - j * 24;
                        __stcs((float4*)(out + ((size_t)(b * 441 + i * 21 + j) * 64
                                                + yv) * 96 + 4 * xq), z4);
                    }
                }
            }
        }
    }

    // zero both stage buffers (unwritten (j,x) slots = OOB x' -> must read 0)
    {
        float4 zv = make_float4(0.f, 0.f, 0.f, 0.f);
        float4* p = (float4*)stage;
        for (int i = td; i < 2 * STAGE_FLOATS / 4; i += NT) p[i] = zv;
    }

    // A frags (fp16, register-resident, sc folded in)
    const float scv = s1[0] * s2[0] / (96.0f * osc[0]);
    uint32_t A[6][4];
    {
        int xg = 2 * (16 * m + g) + par;
        int xg8 = xg + 16;
        const float* p0 = d1 + ((size_t)(b * 96) * 64 + y) * 96;
        #pragma unroll
        for (int kp = 0; kp < 6; ++kp) {
            const float* pc = p0 + (size_t)(16 * kp + 2 * q) * 6144;
            A[kp][0] = packh2(pc[xg] * scv,             pc[6144 + xg] * scv);
            A[kp][1] = packh2(pc[xg8] * scv,            pc[6144 + xg8] * scv);
            A[kp][2] = packh2(pc[8 * 6144 + xg] * scv,  pc[9 * 6144 + xg] * scv);
            A[kp][3] = packh2(pc[8 * 6144 + xg8] * scv, pc[9 * 6144 + xg8] * scv);
        }
    }

    float acc[5][4];
    #pragma unroll
    for (int tt = 0; tt < 5; ++tt)
        #pragma unroll
        for (int e = 0; e < 4; ++e) acc[tt][e] = 0.f;

    const size_t gbase = (size_t)(b * 64) * B_U32;
    const int xbase = 32 * m + 2 * g + par;

    auto prefetch = [&](int s_idx, int bi) {
        if (s_idx <= SC) {                 // rows in [s_lo, SC] always valid
            int row = y0 - 20 + 2 * s_idx;
            const char* gp = (const char*)(g_B + gbase + (size_t)row * B_U32);
            uint32_t sa = bsm_u + bi * B_BYTES;
            #pragma unroll
            for (int u = 0; u < 4; ++u) {
                int idx = u * NT + td;
                if (idx < 1344)
                    asm volatile("cp.async.cg.shared.global [%0], [%1], 16;"
                                 :: "r"(sa + idx * 16), "l"(gp + idx * 16)
                                 : "memory");
            }
        }
        asm volatile("cp.async.commit_group;" ::: "memory");
    };

    prefetch(s_lo, s_lo % NBUF);
    prefetch(s_lo + 1, (s_lo + 1) % NBUF);

    for (int s = s_lo; s <= SC + 1; ++s) {
        asm volatile("cp.async.wait_group 1;" ::: "memory");   // P(s) done
        __syncthreads();

        // P(s+2) into buffer (s+2)%3: last read in compute(s-1), retired above.
        prefetch(s + 2, (s + 2) % NBUF);

        // ---- writeout of staged step s-1 (other stage buffer) ----
        if (s > s_lo) {
            const float* stb = stage + ((s - 1) & 1) * STAGE_FLOATS;
            writeout_half(out, stb,           b, y0,     s - 1, td);
            writeout_half(out, stb + STAGE_H, b, y0 + 2, s - 2, td);
        }

        // ---- compute(s) into stage buffer s&1 ----
        if (s <= SC) {
            const bool a0 = (h == 0) ? (s <= 20) : (s >= 1);   // this warp's i
            if (a0) {
                const uint32_t* bb = bsm + (s % NBUF) * B_U32 + par * 2688
                                     + t0 * 384 + 4 * l;
                #pragma unroll
                for (int kp2 = 0; kp2 < 3; ++kp2) {
                    #pragma unroll
                    for (int tt = 0; tt < 5; ++tt) {
                        if (tt < nt) {
                            uint4 v = *(const uint4*)(bb + tt * 384 + kp2 * 128);
                            mma16(acc[tt], A[2 * kp2],     v.x, v.y);
                            mma16(acc[tt], A[2 * kp2 + 1], v.z, v.w);
                        }
                    }
                }
                // stage accs in output coords: stage[j][x]
                float* stg = stage + (s & 1) * STAGE_FLOATS + h * STAGE_H;
                #pragma unroll
                for (int tt = 0; tt < 5; ++tt) {
                    if (tt < nt) {
                        int j0 = 8 * (t0 + tt + 1) + 2 * q - 16 * m - g;
                        int j1 = j0 - 8;
                        if ((unsigned)j0 < 21u)       stg[j0 * XROW + xbase]            = acc[tt][0];
                        if ((unsigned)(j0 + 1) < 21u) stg[(j0 + 1) * XROW + xbase]      = acc[tt][1];
                        if ((unsigned)j1 < 21u)       stg[j1 * XROW + xbase + 16]       = acc[tt][2];
                        if ((unsigned)(j1 + 1) < 21u) stg[(j1 + 1) * XROW + xbase + 16] = acc[tt][3];
                        acc[tt][0] = acc[tt][1] = acc[tt][2] = acc[tt][3] = 0.f;
                    }
                }
            }
        }
    }
}

extern "C" void kernel_launch(void* const* d_in, const int* in_sizes, int n_in,
                              void* d_out, int out_size) {
    const float* data1     = (const float*)d_in[0];
    const float* data2     = (const float*)d_in[1];
    const float* scale1    = (const float*)d_in[2];
    const float* scale2    = (const float*)d_in[3];
    /* d_in[4] = inter_scale, unused by the reference math */
    const float* out_scale = (const float*)d_in[5];

    reformat<<<512, 256>>>(data2);

    cudaFuncSetAttribute(corr_mma, cudaFuncAttributeMaxDynamicSharedMemorySize,
                         SMEM_BYTES);
    dim3 grid(32, 8);   // (y-pair, b)
    corr_mma<<<grid, NT, SMEM_BYTES>>>(data1, scale1, scale2, out_scale,
                                       (float*)d_out);
}

// round 15
// speedup vs baseline: 1.1606x; 1.1606x over previous
#include <cuda_runtime.h>
#include <cuda_fp16.h>
#include <cstdint>
#include <cstddef>

// Correlation as band-Gram fp16 mma.sync GEMM (m16n8k16, fp32 accumulate).
// Pass 1: reformat d2 -> g_B, per (b,row): [par][t:7][kp2:3][lane:32][e:4].
// Pass 2: block = (y-pair, b), 384 thr, 2 blocks/SM. Rows y0, y0+2 share B
//   rows; 23 uniform steps, one barrier each. B via cp.async double buffer
//   (WAR-safe order). Stage in output coords [j][x]; writeout = raw copy
//   (sc folded into the A fp16 pack). Tile count templated (no predicated
//   waste on 4-tile warps).

#define NT   384
#define XROW 100                           // stage row stride (floats)
#define STAGE_H (21 * XROW)                // 2100 floats per y-half
#define STAGE_FLOATS (2 * STAGE_H)         // 4200 per buffer
#define B_U32   5376                       // u32 words per row (2 par x 2688)
#define B_BYTES 21504
#define STAGE_OFF_B (2 * B_BYTES)          // 43008
#define SMEM_BYTES (STAGE_OFF_B + 2 * STAGE_FLOATS * 4)   // 76608 -> 2 blk/SM

#define GB_N 2752512                       // 8*64*5376
__device__ uint32_t g_B[GB_N];

__device__ __forceinline__ uint32_t packh2(float a, float b) {
    __half2 h = __floats2half2_rn(a, b);
    return *(uint32_t*)&h;
}
__device__ __forceinline__ uint32_t s2u(const void* p) {
    uint32_t a;
    asm("{ .reg .u64 t; cvta.to.shared.u64 t, %1; cvt.u32.u64 %0, t; }"
        : "=r"(a) : "l"(p));
    return a;
}
__device__ __forceinline__ void mma16(float* c, const uint32_t* a,
                                      uint32_t b0, uint32_t b1) {
    asm volatile(
        "mma.sync.aligned.m16n8k16.row.col.f32.f16.f16.f32 "
        "{%0,%1,%2,%3}, {%4,%5,%6,%7}, {%8,%9}, {%0,%1,%2,%3};"
        : "+f"(c[0]), "+f"(c[1]), "+f"(c[2]), "+f"(c[3])
        : "r"(a[0]), "r"(a[1]), "r"(a[2]), "r"(a[3]), "r"(b0), "r"(b1));
}

// ---------------- pass 1: reformat d2 -> g_B (smem transpose) --------------
__global__ void __launch_bounds__(256) reformat(const float* __restrict__ d2) {
    __shared__ float t[96 * 100];
    const int td  = threadIdx.x;
    const int row = blockIdx.x & 63;
    const int b   = blockIdx.x >> 6;

    const float* src = d2 + ((size_t)b * 96 * 64 + row) * 96;
    #pragma unroll
    for (int it = 0; it < 9; ++it) {
        int lin = it * 256 + td;
        int c = lin / 24, xq = lin - c * 24;
        float4 v = *(const float4*)(src + (size_t)c * 6144 + 4 * xq);
        *(float4*)(t + c * 100 + 4 * xq) = v;
    }
    __syncthreads();

    uint32_t* dst = g_B + (size_t)(b * 64 + row) * B_U32;
    #pragma unroll
    for (int it = 0; it < 21; ++it) {      // 5376 words
        int lin = it * 256 + td;
        int e = lin & 3;
        int l = (lin >> 2) & 31;
        int blk = lin >> 7;                // ((par*7 + tt)*3 + kp2)
        int kp2 = blk % 3, pt = blk / 3;
        int tt = pt % 7, par = pt / 7;
        int g = l >> 2, q = l & 3;
        int kp = 2 * kp2 + (e >> 1);
        int c = 16 * kp + 2 * q + 8 * (e & 1);
        int x = 16 * tt + 2 * g - 4 + par;
        float v0 = 0.f, v1 = 0.f;
        if ((unsigned)x < 96u) { v0 = t[c * 100 + x]; v1 = t[(c + 1) * 100 + x]; }
        dst[lin] = packh2(v0, v1);
    }
}

// ---------------- pass 2 helpers ----------------
template <int NTT>
__device__ __forceinline__ void compute_tiles(
    float (*acc)[4], const uint32_t (*A)[4], const uint32_t* bb,
    float* stg, int t0, int m, int g, int q, int xbase)
{
    #pragma unroll
    for (int kp2 = 0; kp2 < 3; ++kp2) {
        #pragma unroll
        for (int tt = 0; tt < NTT; ++tt) {
            uint4 v = *(const uint4*)(bb + tt * 384 + kp2 * 128);
            mma16(acc[tt], A[2 * kp2],     v.x, v.y);
            mma16(acc[tt], A[2 * kp2 + 1], v.z, v.w);
        }
    }
    // stage accs in output coords: stage[j][x]
    #pragma unroll
    for (int tt = 0; tt < NTT; ++tt) {
        int j0 = 8 * (t0 + tt + 1) + 2 * q - 16 * m - g;
        int j1 = j0 - 8;
        if ((unsigned)j0 < 21u)       stg[j0 * XROW + xbase]            = acc[tt][0];
        if ((unsigned)(j0 + 1) < 21u) stg[(j0 + 1) * XROW + xbase]      = acc[tt][1];
        if ((unsigned)j1 < 21u)       stg[j1 * XROW + xbase + 16]       = acc[tt][2];
        if ((unsigned)(j1 + 1) < 21u) stg[(j1 + 1) * XROW + xbase + 16] = acc[tt][3];
        acc[tt][0] = acc[tt][1] = acc[tt][2] = acc[tt][3] = 0.f;
    }
}

__device__ __forceinline__ void writeout_half(
    float* __restrict__ out, const float* __restrict__ stb,
    int b, int yv, int iv, bool vv, int td)
{
    if ((unsigned)iv >= 21u) return;
    float* ob = out + ((size_t)(b * 441 + iv * 21) * 64 + yv) * 96;
    #pragma unroll
    for (int rep = 0; rep < 2; ++rep) {
        int uu = td + NT * rep;
        if (uu < 504) {
            int j = uu / 24, xq = uu - j * 24;
            float4 o;
            if (vv) o = *(const float4*)(stb + j * XROW + 4 * xq);
            else    o = make_float4(0.f, 0.f, 0.f, 0.f);
            __stcs((float4*)(ob + (size_t)j * 6144 + 4 * xq), o);
        }
    }
}

// ---------------- pass 2: paired-y GEMM ----------------
__global__ void __launch_bounds__(NT, 2) corr_mma(
    const float* __restrict__ d1,
    const float* __restrict__ s1, const float* __restrict__ s2,
    const float* __restrict__ osc, float* __restrict__ out)
{
    extern __shared__ char smc[];
    uint32_t* bsm = (uint32_t*)smc;                  // [2][B_U32]
    float* stage = (float*)(smc + STAGE_OFF_B);      // [2 buf][2h][21 j][XROW]
    const uint32_t bsm_u = s2u(smc);

    const int td = threadIdx.x;
    const int w = td >> 5, l = td & 31;
    const int h = w / 6, w6 = w % 6, m = w6 >> 1, par = w6 & 1;
    const int g = l >> 2, q = l & 3;
    const int t0 = (m == 0) ? 0 : ((m == 1) ? 1 : 3);

    const int yp = blockIdx.x;
    const int y0 = 4 * (yp >> 1) + (yp & 1);
    const int b = blockIdx.y;
    const int y = y0 + 2 * h;

    // zero both stage buffers (unwritten (j,x) slots = OOB x' -> must read 0)
    {
        float4 zv = make_float4(0.f, 0.f, 0.f, 0.f);
        float4* p = (float4*)stage;
        for (int i = td; i < 2 * STAGE_FLOATS / 4; i += NT) p[i] = zv;
    }

    // A frags (fp16, register-resident, sc folded in)
    const float scv = s1[0] * s2[0] / (96.0f * osc[0]);
    uint32_t A[6][4];
    {
        int xg = 2 * (16 * m + g) + par;
        int xg8 = xg + 16;
        const float* p0 = d1 + ((size_t)(b * 96) * 64 + y) * 96;
        #pragma unroll
        for (int kp = 0; kp < 6; ++kp) {
            const float* pc = p0 + (size_t)(16 * kp + 2 * q) * 6144;
            A[kp][0] = packh2(pc[xg] * scv,             pc[6144 + xg] * scv);
            A[kp][1] = packh2(pc[xg8] * scv,            pc[6144 + xg8] * scv);
            A[kp][2] = packh2(pc[8 * 6144 + xg] * scv,  pc[9 * 6144 + xg] * scv);
            A[kp][3] = packh2(pc[8 * 6144 + xg8] * scv, pc[9 * 6144 + xg8] * scv);
        }
    }

    float acc[5][4];
    #pragma unroll
    for (int tt = 0; tt < 5; ++tt)
        #pragma unroll
        for (int e = 0; e < 4; ++e) acc[tt][e] = 0.f;

    const size_t gbase = (size_t)(b * 64) * B_U32;
    const int xbase = 32 * m + 2 * g + par;

    auto prefetch = [&](int s_idx, int bi) {
        int row = y0 - 20 + 2 * s_idx;
        if (s_idx <= 21 && (unsigned)row < 64u) {
            const char* gp = (const char*)(g_B + gbase + (size_t)row * B_U32);
            uint32_t sa = bsm_u + bi * B_BYTES;
            #pragma unroll
            for (int u = 0; u < 4; ++u) {
                int idx = u * NT + td;
                if (idx < 1344)
                    asm volatile("cp.async.cg.shared.global [%0], [%1], 16;"
                                 :: "r"(sa + idx * 16), "l"(gp + idx * 16)
                                 : "memory");
            }
        }
        asm volatile("cp.async.commit_group;" ::: "memory");
    };

    prefetch(0, 0);

    for (int s = 0; s < 23; ++s) {
        asm volatile("cp.async.wait_group 0;" ::: "memory");
        __syncthreads();

        // P(s+1) into buffer (s+1)&1: last read in compute(s-1), retired above.
        prefetch(s + 1, (s + 1) & 1);

        // ---- writeout of staged step s-1 (other stage buffer) ----
        if (s >= 1) {
            const float* stb = stage + ((s - 1) & 1) * STAGE_FLOATS;
            bool vp = (unsigned)(y0 + 2 * (s - 1) - 20) < 64u;
            writeout_half(out, stb,           b, y0,     s - 1, vp, td);
            writeout_half(out, stb + STAGE_H, b, y0 + 2, s - 2, vp, td);
        }

        // ---- compute(s) into stage buffer s&1 ----
        const int r = y0 + 2 * s - 20;
        const bool vr = (unsigned)r < 64u;
        const int i = s - h;
        if (s <= 21 && vr && (unsigned)i < 21u) {
            const uint32_t* bb = bsm + (s & 1) * B_U32 + par * 2688
                                 + t0 * 384 + 4 * l;
            float* stg = stage + (s & 1) * STAGE_FLOATS + h * STAGE_H;
            if (m == 1) compute_tiles<5>(acc, A, bb, stg, t0, m, g, q, xbase);
            else        compute_tiles<4>(acc, A, bb, stg, t0, m, g, q, xbase);
        }
    }
}

extern "C" void kernel_launch(void* const* d_in, const int* in_sizes, int n_in,
                              void* d_out, int out_size) {
    const float* data1     = (const float*)d_in[0];
    const float* data2     = (const float*)d_in[1];
    const float* scale1    = (const float*)d_in[2];
    const float* scale2    = (const float*)d_in[3];
    /* d_in[4] = inter_scale, unused by the reference math */
    const float* out_scale = (const float*)d_in[5];

    reformat<<<512, 256>>>(data2);

    cudaFuncSetAttribute(corr_mma, cudaFuncAttributeMaxDynamicSharedMemorySize,
                         SMEM_BYTES);
    dim3 grid(32, 8);   // (y-pair, b)
    corr_mma<<<grid, NT, SMEM_BYTES>>>(data1, scale1, scale2, out_scale,
                                       (float*)d_out);
}